// round 1
// baseline (speedup 1.0000x reference)
#include <cuda_runtime.h>
#include <math.h>

#define NUM_B 8192
#define T_LEN 1024
#define HID   64
#define EPSF  1e-6f

// Per-row derived constants (SoA for coalesced loads in the scan kernel).
__device__ float g_l[NUM_B], g_g[NUM_B], g_a[NUM_B], g_c0[NUM_B],
                 g_uf1[NUM_B], g_uf0[NUM_B], g_prior[NUM_B];

// ---------------------------------------------------------------------------
// Kernel 1: embed gather + MLP + sigmoid head + derived-constant computation.
// Block = 512 threads = 8 rows x 64 units. Weights staged in shared memory.
// ---------------------------------------------------------------------------
__global__ __launch_bounds__(512) void mlp_kernel(
    const int*   __restrict__ X,
    const float* __restrict__ embed,
    const float* __restrict__ W0, const float* __restrict__ b0,
    const float* __restrict__ W1, const float* __restrict__ b1,
    const float* __restrict__ Wout, const float* __restrict__ bout)
{
    __shared__ float sW0[HID * HID];
    __shared__ float sW1[HID * HID];
    __shared__ float sWo[HID * 4];
    __shared__ float sb0[HID], sb1[HID], sbo[4];
    __shared__ float sh[8][HID];
    __shared__ float sp[8][4];

    const int t = threadIdx.x;
    for (int i = t; i < HID * HID; i += 512) { sW0[i] = W0[i]; sW1[i] = W1[i]; }
    if (t < HID * 4) sWo[t] = Wout[t];
    if (t < HID)    { sb0[t] = b0[t]; sb1[t] = b1[t]; }
    if (t < 4)       sbo[t] = bout[t];

    const int j   = t & 63;
    const int r   = t >> 6;
    const int row = blockIdx.x * 8 + r;

    const int xi = X[row];
    const float hv = embed[(size_t)xi * HID + j];
    sh[r][j] = hv;
    __syncthreads();

    // Layer 0
    float acc = sb0[j];
#pragma unroll
    for (int i = 0; i < HID; i++) acc = fmaf(sh[r][i], sW0[i * HID + j], acc);
    acc = fmaxf(acc, 0.0f);
    __syncthreads();
    sh[r][j] = acc;
    __syncthreads();

    // Layer 1
    float acc1 = sb1[j];
#pragma unroll
    for (int i = 0; i < HID; i++) acc1 = fmaf(sh[r][i], sW1[i * HID + j], acc1);
    acc1 = fmaxf(acc1, 0.0f);
    __syncthreads();
    sh[r][j] = acc1;
    __syncthreads();

    // Output head: 4 units per row, computed by threads j<4.
    if (j < 4) {
        float acc2 = sbo[j];
#pragma unroll
        for (int i = 0; i < HID; i++) acc2 = fmaf(sh[r][i], sWo[i * 4 + j], acc2);
        float pv = 1.0f / (1.0f + expf(-acc2));          // sigmoid (accurate expf)
        pv = fminf(fmaxf(pv, EPSF), 1.0f - EPSF);        // clip like reference
        sp[r][j] = pv;
    }
    __syncthreads();

    // Derived per-row constants for the scan:
    //   den(y=1) = g  + a*latent        a  = 1 - s - g
    //   den(y=0) = c0 - a*latent        c0 = 1 - g
    //   next     = l + latent*uf_y * rcp(den)
    //   uf1 = (1-s)(1-l),  uf0 = s(1-l)
    if (j == 0) {
        const float l  = sp[r][0];
        const float gg = sp[r][1];
        const float s  = sp[r][2];
        const float pr = sp[r][3];
        const float a  = 1.0f - s - gg;
        g_l[row]   = l;
        g_g[row]   = gg;
        g_a[row]   = a;
        g_c0[row]  = 1.0f - gg;
        g_uf1[row] = (1.0f - s) * (1.0f - l);
        g_uf0[row] = s * (1.0f - l);
        g_prior[row] = pr;
    }
}

// ---------------------------------------------------------------------------
// Kernel 2: per-row BKT scan. One thread per row. Critical chain per step:
//   FFMA(den) -> MUFU.RCP -> FFMA(next) -> FMNMX  = 28 cycles.
// y software-pipelined 2 groups (32 steps ~ 900 cyc) ahead; outputs via STG.128.
// ---------------------------------------------------------------------------
__global__ __launch_bounds__(32) void bkt_kernel(
    const int* __restrict__ y, float* __restrict__ out)
{
    const int row = blockIdx.x * 32 + threadIdx.x;

    const float l   = g_l[row];
    const float gg  = g_g[row];
    const float a   = g_a[row];
    const float c0  = g_c0[row];
    const float uf1 = g_uf1[row];
    const float uf0 = g_uf0[row];
    const float na  = -a;
    const float HI  = 1.0f - EPSF;

    float latent = g_prior[row];

    const int4* yrow = reinterpret_cast<const int4*>(y + (size_t)row * T_LEN);
    float4* outc = reinterpret_cast<float4*>(out) + (size_t)row * (T_LEN / 4);
    float4* outl = reinterpret_cast<float4*>(out) +
                   (size_t)NUM_B * (T_LEN / 4) + (size_t)row * (T_LEN / 4);

#define STEP(yv, co, lo) do {                                         \
        const bool  p  = (yv) > 0;                                    \
        const float at = p ? a   : na;                                \
        const float ct = p ? gg  : c0;                                \
        const float uf = p ? uf1 : uf0;                               \
        const float den = fmaf(latent, at, ct);                       \
        const float m   = latent * uf;                                \
        float rr;                                                     \
        asm("rcp.approx.ftz.f32 %0, %1;" : "=f"(rr) : "f"(den));      \
        (co) = fmaf(latent, a, gg);   /* 'correct' output */          \
        (lo) = latent;                /* pre-update latent */         \
        latent = fminf(fmaf(m, rr, l), HI);                           \
    } while (0)

    // Groups of 16 steps (4 x int4 of y). Prefetch depth 2 groups.
    int4 buf[8];
#pragma unroll
    for (int i = 0; i < 8; i++) buf[i] = yrow[i];

    const int NGROUPS = T_LEN / 16;  // 64
#pragma unroll 1
    for (int gq = 0; gq < NGROUPS; gq++) {
        int4 c0v = buf[0], c1v = buf[1], c2v = buf[2], c3v = buf[3];
        buf[0] = buf[4]; buf[1] = buf[5]; buf[2] = buf[6]; buf[3] = buf[7];
        if (gq + 2 < NGROUPS) {
            buf[4] = yrow[4 * gq + 8];
            buf[5] = yrow[4 * gq + 9];
            buf[6] = yrow[4 * gq + 10];
            buf[7] = yrow[4 * gq + 11];
        }

        float4 cv, lv;
        STEP(c0v.x, cv.x, lv.x); STEP(c0v.y, cv.y, lv.y);
        STEP(c0v.z, cv.z, lv.z); STEP(c0v.w, cv.w, lv.w);
        outc[4 * gq + 0] = cv;  outl[4 * gq + 0] = lv;

        STEP(c1v.x, cv.x, lv.x); STEP(c1v.y, cv.y, lv.y);
        STEP(c1v.z, cv.z, lv.z); STEP(c1v.w, cv.w, lv.w);
        outc[4 * gq + 1] = cv;  outl[4 * gq + 1] = lv;

        STEP(c2v.x, cv.x, lv.x); STEP(c2v.y, cv.y, lv.y);
        STEP(c2v.z, cv.z, lv.z); STEP(c2v.w, cv.w, lv.w);
        outc[4 * gq + 2] = cv;  outl[4 * gq + 2] = lv;

        STEP(c3v.x, cv.x, lv.x); STEP(c3v.y, cv.y, lv.y);
        STEP(c3v.z, cv.z, lv.z); STEP(c3v.w, cv.w, lv.w);
        outc[4 * gq + 3] = cv;  outl[4 * gq + 3] = lv;
    }
#undef STEP
}

// ---------------------------------------------------------------------------
extern "C" void kernel_launch(void* const* d_in, const int* in_sizes, int n_in,
                              void* d_out, int out_size)
{
    const int*   X     = (const int*)  d_in[0];
    const int*   y     = (const int*)  d_in[1];
    const float* embed = (const float*)d_in[2];
    const float* W0    = (const float*)d_in[3];
    const float* b0    = (const float*)d_in[4];
    const float* W1    = (const float*)d_in[5];
    const float* b1    = (const float*)d_in[6];
    const float* Wout  = (const float*)d_in[7];
    const float* bout  = (const float*)d_in[8];

    mlp_kernel<<<NUM_B / 8, 512>>>(X, embed, W0, b0, W1, b1, Wout, bout);
    bkt_kernel<<<NUM_B / 32, 32>>>(y, (float*)d_out);
}

// round 2
// speedup vs baseline: 1.1142x; 1.1142x over previous
#include <cuda_runtime.h>
#include <math.h>

#define NUM_B 8192
#define T_LEN 1024
#define HID   64
#define EPSF  1e-6f
#define YPAD  68   // ints per row in smem: 68*4=272B (16B aligned), banks 4t..4t+3 conflict-free

// Per-row derived constants (SoA).
__device__ float g_l[NUM_B], g_g[NUM_B], g_a[NUM_B], g_c0[NUM_B],
                 g_uf1[NUM_B], g_uf0[NUM_B], g_prior[NUM_B];

// ---------------------------------------------------------------------------
// Kernel 1: embed gather + MLP + sigmoid head. 32 rows/block (weights staged
// once per 32 rows instead of per 8).
// ---------------------------------------------------------------------------
__global__ __launch_bounds__(512) void mlp_kernel(
    const int*   __restrict__ X,
    const float* __restrict__ embed,
    const float* __restrict__ W0, const float* __restrict__ b0,
    const float* __restrict__ W1, const float* __restrict__ b1,
    const float* __restrict__ Wout, const float* __restrict__ bout)
{
    __shared__ float sW0[HID * HID];
    __shared__ float sW1[HID * HID];
    __shared__ float sWo[HID * 4];
    __shared__ float sb0[HID], sb1[HID], sbo[4];
    __shared__ float sh[8][HID];
    __shared__ float sp[8][4];

    const int t = threadIdx.x;
    for (int i = t; i < HID * HID; i += 512) { sW0[i] = W0[i]; sW1[i] = W1[i]; }
    if (t < HID * 4) sWo[t] = Wout[t];
    if (t < HID)    { sb0[t] = b0[t]; sb1[t] = b1[t]; }
    if (t < 4)       sbo[t] = bout[t];

    const int j = t & 63;
    const int r = t >> 6;
    __syncthreads();

#pragma unroll 1
    for (int it = 0; it < 4; ++it) {
        const int row = blockIdx.x * 32 + it * 8 + r;

        const int xi = X[row];
        sh[r][j] = embed[(size_t)xi * HID + j];
        __syncthreads();

        float acc = sb0[j];
#pragma unroll
        for (int i = 0; i < HID; i++) acc = fmaf(sh[r][i], sW0[i * HID + j], acc);
        acc = fmaxf(acc, 0.0f);
        __syncthreads();
        sh[r][j] = acc;
        __syncthreads();

        float acc1 = sb1[j];
#pragma unroll
        for (int i = 0; i < HID; i++) acc1 = fmaf(sh[r][i], sW1[i * HID + j], acc1);
        acc1 = fmaxf(acc1, 0.0f);
        __syncthreads();
        sh[r][j] = acc1;
        __syncthreads();

        if (j < 4) {
            float acc2 = sbo[j];
#pragma unroll
            for (int i = 0; i < HID; i++) acc2 = fmaf(sh[r][i], sWo[i * 4 + j], acc2);
            float pv = 1.0f / (1.0f + expf(-acc2));
            pv = fminf(fmaxf(pv, EPSF), 1.0f - EPSF);
            sp[r][j] = pv;
        }
        __syncthreads();

        if (j == 0) {
            const float l  = sp[r][0];
            const float gg = sp[r][1];
            const float s  = sp[r][2];
            const float pr = sp[r][3];
            const float a  = 1.0f - s - gg;
            g_l[row]   = l;
            g_g[row]   = gg;
            g_a[row]   = a;
            g_c0[row]  = 1.0f - gg;
            g_uf1[row] = (1.0f - s) * (1.0f - l);
            g_uf0[row] = s * (1.0f - l);
            g_prior[row] = pr;
        }
        __syncthreads();
    }
}

// ---------------------------------------------------------------------------
// Kernel 2: BKT scan. Block = 64 threads (2 independent warps on SMSP 0,1),
// grid = 128 (1 block/SM on 128 SMs). Each warp owns 32 rows; y is staged
// through smem via cp.async with row-coalesced loads (double-buffered 64-step
// tiles). Scan chain per step: FFMA(4) -> MUFU.RCP(16) -> FFMA(4) -> FMNMX(4).
// ---------------------------------------------------------------------------
__device__ __forceinline__ unsigned smem_u32(const void* p) {
    return (unsigned)__cvta_generic_to_shared(p);
}

__global__ __launch_bounds__(64) void bkt_kernel(
    const int* __restrict__ y, float* __restrict__ out)
{
    __shared__ __align__(16) int s_y[2][2][32][YPAD];  // [warp][buf][row][step]

    const int warp = threadIdx.x >> 5;
    const int lane = threadIdx.x & 31;
    const int rowbase = (blockIdx.x * 2 + warp) * 32;
    const int row = rowbase + lane;

    const float l   = g_l[row];
    const float gg  = g_g[row];
    const float a   = g_a[row];
    const float c0  = g_c0[row];
    const float uf1 = g_uf1[row];
    const float uf0 = g_uf0[row];
    const float na  = -a;
    const float HI  = 1.0f - EPSF;
    float latent    = g_prior[row];

    // cp.async lane mapping: 2 rows per warp instruction, 16B per lane.
    const int r2 = lane >> 4;          // 0 or 1: which of the 2 rows
    const int c4 = (lane & 15) * 4;    // int offset within the 64-step tile
    const int* yw = y + (size_t)rowbase * T_LEN;

#define LOAD_TILE(K, B) do {                                                  \
        _Pragma("unroll")                                                     \
        for (int i = 0; i < 16; ++i) {                                        \
            const int rr = 2 * i + r2;                                        \
            const int* src = yw + (size_t)rr * T_LEN + (K) * 64 + c4;         \
            unsigned dst = smem_u32(&s_y[warp][(B)][rr][c4]);                 \
            asm volatile("cp.async.cg.shared.global [%0], [%1], 16;"          \
                         :: "r"(dst), "l"(src));                              \
        }                                                                     \
        asm volatile("cp.async.commit_group;" ::: "memory");                  \
    } while (0)

    LOAD_TILE(0, 0);
    LOAD_TILE(1, 1);

    float* outc = out + (size_t)row * T_LEN;
    float* outl = out + (size_t)NUM_B * T_LEN + (size_t)row * T_LEN;

#define STEP(yv, co, lo) do {                                         \
        const bool  p  = (yv) > 0;                                    \
        const float at = p ? a   : na;                                \
        const float ct = p ? gg  : c0;                                \
        const float uf = p ? uf1 : uf0;                               \
        const float den = fmaf(latent, at, ct);                       \
        const float m   = latent * uf;                                \
        float rr_;                                                    \
        asm("rcp.approx.ftz.f32 %0, %1;" : "=f"(rr_) : "f"(den));     \
        (co) = fmaf(latent, a, gg);                                   \
        (lo) = latent;                                                \
        latent = fminf(fmaf(m, rr_, l), HI);                          \
    } while (0)

#pragma unroll 1
    for (int k = 0; k < 16; ++k) {
        const int b = k & 1;
        asm volatile("cp.async.wait_group 1;" ::: "memory");
        __syncwarp();

#pragma unroll
        for (int sub = 0; sub < 4; ++sub) {
            const int* yt = &s_y[warp][b][lane][sub * 16];
            const int4 q0 = *reinterpret_cast<const int4*>(yt + 0);
            const int4 q1 = *reinterpret_cast<const int4*>(yt + 4);
            const int4 q2 = *reinterpret_cast<const int4*>(yt + 8);
            const int4 q3 = *reinterpret_cast<const int4*>(yt + 12);

            const int s0 = k * 64 + sub * 16;
            float4 cv, lv;

            STEP(q0.x, cv.x, lv.x); STEP(q0.y, cv.y, lv.y);
            STEP(q0.z, cv.z, lv.z); STEP(q0.w, cv.w, lv.w);
            *reinterpret_cast<float4*>(outc + s0 + 0) = cv;
            *reinterpret_cast<float4*>(outl + s0 + 0) = lv;

            STEP(q1.x, cv.x, lv.x); STEP(q1.y, cv.y, lv.y);
            STEP(q1.z, cv.z, lv.z); STEP(q1.w, cv.w, lv.w);
            *reinterpret_cast<float4*>(outc + s0 + 4) = cv;
            *reinterpret_cast<float4*>(outl + s0 + 4) = lv;

            STEP(q2.x, cv.x, lv.x); STEP(q2.y, cv.y, lv.y);
            STEP(q2.z, cv.z, lv.z); STEP(q2.w, cv.w, lv.w);
            *reinterpret_cast<float4*>(outc + s0 + 8) = cv;
            *reinterpret_cast<float4*>(outl + s0 + 8) = lv;

            STEP(q3.x, cv.x, lv.x); STEP(q3.y, cv.y, lv.y);
            STEP(q3.z, cv.z, lv.z); STEP(q3.w, cv.w, lv.w);
            *reinterpret_cast<float4*>(outc + s0 + 12) = cv;
            *reinterpret_cast<float4*>(outl + s0 + 12) = lv;
        }

        __syncwarp();   // all lanes done reading buffer b before refill
        if (k < 14) {
            LOAD_TILE(k + 2, b);
        } else {
            asm volatile("cp.async.commit_group;" ::: "memory");
        }
    }
#undef STEP
#undef LOAD_TILE
}

// ---------------------------------------------------------------------------
extern "C" void kernel_launch(void* const* d_in, const int* in_sizes, int n_in,
                              void* d_out, int out_size)
{
    const int*   X     = (const int*)  d_in[0];
    const int*   y     = (const int*)  d_in[1];
    const float* embed = (const float*)d_in[2];
    const float* W0    = (const float*)d_in[3];
    const float* b0    = (const float*)d_in[4];
    const float* W1    = (const float*)d_in[5];
    const float* b1    = (const float*)d_in[6];
    const float* Wout  = (const float*)d_in[7];
    const float* bout  = (const float*)d_in[8];

    mlp_kernel<<<NUM_B / 32, 512>>>(X, embed, W0, b0, W1, b1, Wout, bout);
    bkt_kernel<<<NUM_B / 64, 64>>>(y, (float*)d_out);
}